// round 1
// baseline (speedup 1.0000x reference)
#include <cuda_runtime.h>
#include <cstdint>

// MultiHeadAttention: B=4, I=J=2048, WIDTH=1024, HEADS=16, HEAD_DIM=64
// Outputs (concatenated): out [4,2048,1024] fp32, attn_weight [4,16,2048,2048] fp32
//
// Pipeline (all tf32 mma.sync m16n8k8, rna-rounded):
//   1-3. proj_kernel:   Qp/Kp/Vp = x @ W^T   (M=8192,N=1024,K=1024)
//   4.   scores_kernel: E = exp(mask(Q K^T)/8) per head, + per-block rowsum partials
//   5.   reduce_sums:   rowsum = sum of 16 partials (deterministic order)
//   6.   pv_kernel:     X[b,i,n*64+d] = (E @ V) * inv_rowsum
//   7.   normalize:     attn_out = E * inv_rowsum (in place)
//   8.   out_kernel:    out = X @ Wo^T
//
// The module's reshape(b,n,i,d) of a (b,i,1024) buffer makes each head's
// Q/K/V a CONTIGUOUS 2048x64 block at offset z*131072 (z = b*16+n).

#define IW 2097152ULL        // I*WIDTH = 2048*1024 (per-batch proj elems)
#define HEADELEMS 131072ULL  // I*HEAD_DIM
#define ATTN_PER_HEAD 4194304ULL // 2048*2048
#define NROWS 131072         // B*H*I = 64*2048

__device__ float g_qp[8388608];
__device__ float g_kp[8388608];
__device__ float g_vp[8388608];
__device__ float g_x [8388608];
__device__ float g_sum[NROWS];
__device__ float g_part[NROWS * 16];

__device__ __forceinline__ uint32_t f2tf(float x) {
    uint32_t u;
    asm("cvt.rna.tf32.f32 %0, %1;" : "=r"(u) : "f"(x));
    return u;
}

__device__ __forceinline__ void mma8(float* c, const uint32_t* a, const uint32_t* b) {
    asm("mma.sync.aligned.m16n8k8.row.col.f32.tf32.tf32.f32 "
        "{%0,%1,%2,%3}, {%4,%5,%6,%7}, {%8,%9}, {%0,%1,%2,%3};"
        : "+f"(c[0]), "+f"(c[1]), "+f"(c[2]), "+f"(c[3])
        : "r"(a[0]), "r"(a[1]), "r"(a[2]), "r"(a[3]), "r"(b[0]), "r"(b[1]));
}

// ---------------------------------------------------------------------------
// Generic 128x128-tile TN GEMM body for M=8192, N=1024, K=1024:
// C[m][n] = sum_k A[m][k] * W[n][k]   (both row-major, K contiguous)
// 256 threads = 8 warps (2 row x 4 col), warp tile 64x32, BK=32.
// ---------------------------------------------------------------------------
__device__ __forceinline__ void gemm1024_body(const float* __restrict__ A,
                                              const float* __restrict__ W,
                                              float* __restrict__ C)
{
    __shared__ uint32_t As[128 * 36];
    __shared__ uint32_t Bs[128 * 36];
    const int tid  = threadIdx.x;
    const int wid  = tid >> 5, lane = tid & 31;
    const int gid  = lane >> 2, tig = lane & 3;
    const int wrow = wid >> 2, wcol = wid & 3;
    const float* Ab = A + (size_t)blockIdx.y * 128 * 1024;
    const float* Bb = W + (size_t)blockIdx.x * 128 * 1024;

    float c[4][4][4];
    #pragma unroll
    for (int mi = 0; mi < 4; mi++)
        #pragma unroll
        for (int ni = 0; ni < 4; ni++)
            #pragma unroll
            for (int r = 0; r < 4; r++) c[mi][ni][r] = 0.f;

    for (int kt = 0; kt < 1024; kt += 32) {
        #pragma unroll
        for (int v = 0; v < 4; v++) {
            int i4 = tid + v * 256;
            int r = i4 >> 3, c4 = (i4 & 7) << 2;
            float4 fa = *(const float4*)(Ab + (size_t)r * 1024 + kt + c4);
            uint32_t* da = &As[r * 36 + c4];
            da[0] = f2tf(fa.x); da[1] = f2tf(fa.y); da[2] = f2tf(fa.z); da[3] = f2tf(fa.w);
            float4 fb = *(const float4*)(Bb + (size_t)r * 1024 + kt + c4);
            uint32_t* db = &Bs[r * 36 + c4];
            db[0] = f2tf(fb.x); db[1] = f2tf(fb.y); db[2] = f2tf(fb.z); db[3] = f2tf(fb.w);
        }
        __syncthreads();
        #pragma unroll
        for (int kk = 0; kk < 32; kk += 8) {
            uint32_t af[4][4], bf[4][2];
            #pragma unroll
            for (int mi = 0; mi < 4; mi++) {
                int m = wrow * 64 + mi * 16 + gid;
                af[mi][0] = As[m * 36 + kk + tig];
                af[mi][1] = As[(m + 8) * 36 + kk + tig];
                af[mi][2] = As[m * 36 + kk + tig + 4];
                af[mi][3] = As[(m + 8) * 36 + kk + tig + 4];
            }
            #pragma unroll
            for (int ni = 0; ni < 4; ni++) {
                int n = wcol * 32 + ni * 8 + gid;
                bf[ni][0] = Bs[n * 36 + kk + tig];
                bf[ni][1] = Bs[n * 36 + kk + tig + 4];
            }
            #pragma unroll
            for (int mi = 0; mi < 4; mi++)
                #pragma unroll
                for (int ni = 0; ni < 4; ni++)
                    mma8(c[mi][ni], af[mi], bf[ni]);
        }
        __syncthreads();
    }

    #pragma unroll
    for (int mi = 0; mi < 4; mi++)
        #pragma unroll
        for (int ni = 0; ni < 4; ni++) {
            int row = blockIdx.y * 128 + wrow * 64 + mi * 16 + gid;
            int col = blockIdx.x * 128 + wcol * 32 + ni * 8 + tig * 2;
            *(float2*)(C + (size_t)row * 1024 + col)       = make_float2(c[mi][ni][0], c[mi][ni][1]);
            *(float2*)(C + (size_t)(row + 8) * 1024 + col) = make_float2(c[mi][ni][2], c[mi][ni][3]);
        }
}

__global__ __launch_bounds__(256, 2)
void proj_kernel(const float* __restrict__ A, const float* __restrict__ W, int which)
{
    float* C = (which == 0) ? g_qp : (which == 1) ? g_kp : g_vp;
    gemm1024_body(A, W, C);
}

__global__ __launch_bounds__(256, 2)
void out_kernel(const float* __restrict__ W, float* __restrict__ C)
{
    gemm1024_body(g_x, W, C);
}

// ---------------------------------------------------------------------------
// Scores: per head z, S = Qh Kh^T (K=64); epilogue: mask, *0.125, exp, write E,
// deterministic per-row partial sums -> g_part[row][blockIdx.x].
// Grid (16 jblk, 16 iblk, 64 heads).
// ---------------------------------------------------------------------------
__global__ __launch_bounds__(256, 2)
void scores_kernel(const unsigned char* __restrict__ mask, float* __restrict__ E)
{
    __shared__ uint32_t As[128 * 36];
    __shared__ uint32_t Bs[128 * 36];
    __shared__ float swsum[4 * 128];
    const int tid  = threadIdx.x;
    const int wid  = tid >> 5, lane = tid & 31;
    const int gid  = lane >> 2, tig = lane & 3;
    const int wrow = wid >> 2, wcol = wid & 3;
    const int z = blockIdx.z;
    const float* Ab = g_qp + (size_t)z * HEADELEMS + (size_t)blockIdx.y * 128 * 64;
    const float* Bb = g_kp + (size_t)z * HEADELEMS + (size_t)blockIdx.x * 128 * 64;

    float c[4][4][4];
    #pragma unroll
    for (int mi = 0; mi < 4; mi++)
        #pragma unroll
        for (int ni = 0; ni < 4; ni++)
            #pragma unroll
            for (int r = 0; r < 4; r++) c[mi][ni][r] = 0.f;

    #pragma unroll
    for (int kt = 0; kt < 64; kt += 32) {
        #pragma unroll
        for (int v = 0; v < 4; v++) {
            int i4 = tid + v * 256;
            int r = i4 >> 3, c4 = (i4 & 7) << 2;
            float4 fa = *(const float4*)(Ab + (size_t)r * 64 + kt + c4);
            uint32_t* da = &As[r * 36 + c4];
            da[0] = f2tf(fa.x); da[1] = f2tf(fa.y); da[2] = f2tf(fa.z); da[3] = f2tf(fa.w);
            float4 fb = *(const float4*)(Bb + (size_t)r * 64 + kt + c4);
            uint32_t* db = &Bs[r * 36 + c4];
            db[0] = f2tf(fb.x); db[1] = f2tf(fb.y); db[2] = f2tf(fb.z); db[3] = f2tf(fb.w);
        }
        __syncthreads();
        #pragma unroll
        for (int kk = 0; kk < 32; kk += 8) {
            uint32_t af[4][4], bf[4][2];
            #pragma unroll
            for (int mi = 0; mi < 4; mi++) {
                int m = wrow * 64 + mi * 16 + gid;
                af[mi][0] = As[m * 36 + kk + tig];
                af[mi][1] = As[(m + 8) * 36 + kk + tig];
                af[mi][2] = As[m * 36 + kk + tig + 4];
                af[mi][3] = As[(m + 8) * 36 + kk + tig + 4];
            }
            #pragma unroll
            for (int ni = 0; ni < 4; ni++) {
                int n = wcol * 32 + ni * 8 + gid;
                bf[ni][0] = Bs[n * 36 + kk + tig];
                bf[ni][1] = Bs[n * 36 + kk + tig + 4];
            }
            #pragma unroll
            for (int mi = 0; mi < 4; mi++)
                #pragma unroll
                for (int ni = 0; ni < 4; ni++)
                    mma8(c[mi][ni], af[mi], bf[ni]);
        }
        __syncthreads();
    }

    const unsigned char* mb = mask + (size_t)(z >> 4) * ATTN_PER_HEAD;
    float* Eh = E + (size_t)z * ATTN_PER_HEAD
                  + (size_t)blockIdx.y * 128 * 2048 + (size_t)blockIdx.x * 128;

    #pragma unroll
    for (int mi = 0; mi < 4; mi++) {
        #pragma unroll
        for (int h = 0; h < 2; h++) {
            int rl = wrow * 64 + mi * 16 + h * 8 + gid;
            size_t gi = (size_t)blockIdx.y * 128 + rl;
            float rs = 0.f;
            #pragma unroll
            for (int ni = 0; ni < 4; ni++) {
                int cl = wcol * 32 + ni * 8 + tig * 2;
                size_t gj = (size_t)blockIdx.x * 128 + cl;
                float s0 = c[mi][ni][h * 2 + 0];
                float s1 = c[mi][ni][h * 2 + 1];
                if (mb[gi * 2048 + gj])     s0 = -1e9f;
                if (mb[gi * 2048 + gj + 1]) s1 = -1e9f;
                float e0 = __expf(s0 * 0.125f);
                float e1 = __expf(s1 * 0.125f);
                *(float2*)(Eh + (size_t)rl * 2048 + cl) = make_float2(e0, e1);
                rs += e0 + e1;
            }
            // deterministic reduce across tig (lanes sharing gid)
            rs += __shfl_xor_sync(0xffffffffu, rs, 1);
            rs += __shfl_xor_sync(0xffffffffu, rs, 2);
            if (tig == 0) swsum[wcol * 128 + rl] = rs;
        }
    }
    __syncthreads();
    if (tid < 128) {
        float p = swsum[tid] + swsum[128 + tid] + swsum[256 + tid] + swsum[384 + tid];
        g_part[((size_t)z * 2048 + blockIdx.y * 128 + tid) * 16 + blockIdx.x] = p;
    }
}

__global__ void reduce_sums_kernel()
{
    int i = blockIdx.x * 256 + threadIdx.x;
    if (i < NROWS) {
        const float* p = &g_part[(size_t)i * 16];
        float s = 0.f;
        #pragma unroll
        for (int j = 0; j < 16; j++) s += p[j];
        g_sum[i] = s;
    }
}

// ---------------------------------------------------------------------------
// PV: per head z, O = E(2048x2048) @ V(2048x64), scaled by 1/rowsum, scattered
// into X[b, i, n*64 + d]. BM=128, BN=64, BK=32, warps 4x2 (warp tile 32x32).
// Grid (1, 16, 64).
// ---------------------------------------------------------------------------
__global__ __launch_bounds__(256, 2)
void pv_kernel(const float* __restrict__ E)
{
    __shared__ uint32_t Es[128 * 36];
    __shared__ uint32_t Vs[32 * 72];
    const int tid  = threadIdx.x;
    const int wid  = tid >> 5, lane = tid & 31;
    const int gid  = lane >> 2, tig = lane & 3;
    const int wrow = wid >> 1, wcol = wid & 1;
    const int z = blockIdx.z;
    const float* Eh = E + (size_t)z * ATTN_PER_HEAD + (size_t)blockIdx.y * 128 * 2048;
    const float* Vh = g_vp + (size_t)z * HEADELEMS;

    float c[2][4][4];
    #pragma unroll
    for (int mi = 0; mi < 2; mi++)
        #pragma unroll
        for (int ni = 0; ni < 4; ni++)
            #pragma unroll
            for (int r = 0; r < 4; r++) c[mi][ni][r] = 0.f;

    for (int kt = 0; kt < 2048; kt += 32) {
        #pragma unroll
        for (int v = 0; v < 4; v++) {
            int i4 = tid + v * 256;
            int r = i4 >> 3, c4 = (i4 & 7) << 2;
            float4 fe = *(const float4*)(Eh + (size_t)r * 2048 + kt + c4);
            uint32_t* de = &Es[r * 36 + c4];
            de[0] = f2tf(fe.x); de[1] = f2tf(fe.y); de[2] = f2tf(fe.z); de[3] = f2tf(fe.w);
        }
        #pragma unroll
        for (int v = 0; v < 2; v++) {
            int f = tid + v * 256;
            int r = f >> 4, c4 = (f & 15) << 2;
            float4 fv = *(const float4*)(Vh + (size_t)(kt + r) * 64 + c4);
            uint32_t* dv = &Vs[r * 72 + c4];
            dv[0] = f2tf(fv.x); dv[1] = f2tf(fv.y); dv[2] = f2tf(fv.z); dv[3] = f2tf(fv.w);
        }
        __syncthreads();
        #pragma unroll
        for (int kk = 0; kk < 32; kk += 8) {
            uint32_t af[2][4], bf[4][2];
            #pragma unroll
            for (int mi = 0; mi < 2; mi++) {
                int m = wrow * 32 + mi * 16 + gid;
                af[mi][0] = Es[m * 36 + kk + tig];
                af[mi][1] = Es[(m + 8) * 36 + kk + tig];
                af[mi][2] = Es[m * 36 + kk + tig + 4];
                af[mi][3] = Es[(m + 8) * 36 + kk + tig + 4];
            }
            #pragma unroll
            for (int ni = 0; ni < 4; ni++) {
                int n = wcol * 32 + ni * 8 + gid;
                bf[ni][0] = Vs[(kk + tig) * 72 + n];
                bf[ni][1] = Vs[(kk + tig + 4) * 72 + n];
            }
            #pragma unroll
            for (int mi = 0; mi < 2; mi++)
                #pragma unroll
                for (int ni = 0; ni < 4; ni++)
                    mma8(c[mi][ni], af[mi], bf[ni]);
        }
        __syncthreads();
    }

    const int b = z >> 4, n = z & 15;
    #pragma unroll
    for (int mi = 0; mi < 2; mi++) {
        #pragma unroll
        for (int h = 0; h < 2; h++) {
            int i = blockIdx.y * 128 + wrow * 32 + mi * 16 + h * 8 + gid;
            float inv = 1.0f / g_sum[(size_t)z * 2048 + i];
            float* Xr = g_x + (size_t)b * IW + (size_t)i * 1024 + n * 64;
            #pragma unroll
            for (int ni = 0; ni < 4; ni++) {
                int d = wcol * 32 + ni * 8 + tig * 2;
                *(float2*)(Xr + d) = make_float2(c[mi][ni][h * 2] * inv,
                                                 c[mi][ni][h * 2 + 1] * inv);
            }
        }
    }
}

__global__ void normalize_kernel(float* __restrict__ E)
{
    const size_t n4 = 268435456ULL / 4;
    const size_t stride = (size_t)gridDim.x * blockDim.x;
    for (size_t i = (size_t)blockIdx.x * blockDim.x + threadIdx.x; i < n4; i += stride) {
        float4 val = *((const float4*)E + i);
        float inv = 1.0f / g_sum[i >> 9];   // 512 float4 per row of 2048
        val.x *= inv; val.y *= inv; val.z *= inv; val.w *= inv;
        *((float4*)E + i) = val;
    }
}

extern "C" void kernel_launch(void* const* d_in, const int* in_sizes, int n_in,
                              void* d_out, int out_size)
{
    const float* q  = (const float*)d_in[0];
    const float* k  = (const float*)d_in[1];
    const float* v  = (const float*)d_in[2];
    const unsigned char* mask = (const unsigned char*)d_in[3];
    const float* Wq = (const float*)d_in[4];
    const float* Wk = (const float*)d_in[5];
    const float* Wv = (const float*)d_in[6];
    const float* Wo = (const float*)d_in[7];

    float* out  = (float*)d_out;            // [4,2048,1024]
    float* attn = out + 8388608;            // [4,16,2048,2048]

    dim3 gProj(8, 64, 1);                   // N/128, M/128
    proj_kernel<<<gProj, 256>>>(q, Wq, 0);
    proj_kernel<<<gProj, 256>>>(k, Wk, 1);
    proj_kernel<<<gProj, 256>>>(v, Wv, 2);

    scores_kernel<<<dim3(16, 16, 64), 256>>>(mask, attn);
    reduce_sums_kernel<<<512, 256>>>();
    pv_kernel<<<dim3(1, 16, 64), 256>>>(attn);
    normalize_kernel<<<2048, 256>>>(attn);
    out_kernel<<<gProj, 256>>>(Wo, out);
}